// round 13
// baseline (speedup 1.0000x reference)
#include <cuda_runtime.h>
#include <cstdint>

#define N 128
#define K 64
#define NPAIRS 2016
#define LLRMAX 100.0f
#define FULLM 0xffffffffu
#define NT 512

__device__ __forceinline__ int nth_set64(unsigned long long w, int j) {
    unsigned lo = (unsigned)w, hi = (unsigned)(w >> 32);
    int c = __popc(lo);
    return (j < c) ? __fns(lo, 0, j + 1) : 32 + __fns(hi, 0, j - c + 1);
}

__global__ __launch_bounds__(NT) void osd_kernel(
    const float* __restrict__ llrs,
    const float* __restrict__ gm,
    const int* __restrict__ t_ptr,
    float* __restrict__ out)
{
    __shared__ float s_llr[N];
    __shared__ float s_key[N];                // llr_sort
    __shared__ int   s_idx[N];
    __shared__ unsigned s_gmq[4][N];          // 16 packed rows per quarter
    __shared__ unsigned long long s_k64[N];   // sort keys, then parity cols
    __shared__ unsigned short s_rp[4][N];     // rank partials
    __shared__ unsigned long long s_P[K];
    __shared__ float s_dinfo[K];
    __shared__ float s_dpar[K];
    __shared__ float s_tab[8 * 256];
    __shared__ unsigned long long s_u, s_Cp;
    __shared__ float s_bsc[16];
    __shared__ int   s_bid[16];

    const int tid  = threadIdx.x;
    const int lane = tid & 31;
    const int wrp  = tid >> 5;
    const int b    = blockIdx.x;

    // ---- hoisted t load ----
    int t = 2;
    if (t_ptr) t = t_ptr[0];
    if (t < 0) t = 0;
    if (t > 2) t = 2;

    // ---- gm pack: each thread packs 16 rows of one column ----
    {
        const int quarter = tid >> 7;         // 0..3
        const int col  = tid & 127;
        const int rbase = quarter << 4;       // 0,16,32,48
        unsigned w = 0u;
        #pragma unroll
        for (int i = 0; i < 16; ++i)
            if (gm[(rbase + i) * N + col] > 0.5f) w |= (1u << i);
        s_gmq[quarter][col] = w;
    }

    // ---- keys for rank sort ----
    if (tid < N) {
        float v = llrs[b * N + tid];
        v = fminf(fmaxf(v, -LLRMAX), LLRMAX);
        s_llr[tid] = v;
        s_k64[tid] = ((unsigned long long)__float_as_uint(fabsf(v)) << 32) |
                     (unsigned long long)(127 - tid);
    }
    __syncthreads();

    // ---- rank sort: thread (i, q) counts chunk q's keys greater than key i ----
    {
        const int i = tid & 127, q = tid >> 7;
        const unsigned long long ki = s_k64[i];
        const unsigned long long* base = s_k64 + q * 32;
        int cnt = 0;
        #pragma unroll
        for (int j = 0; j < 32; ++j) cnt += (base[j] > ki);
        s_rp[q][i] = (unsigned short)cnt;
    }
    __syncthreads();
    if (tid < N) {
        int r = s_rp[0][tid] + s_rp[1][tid] + s_rp[2][tid] + s_rp[3][tid];
        s_idx[r] = tid;          // rank r (descending) holds original index tid
        s_key[r] = s_llr[tid];
    }
    __syncthreads();

    // ---- pair decomposition (pure ALU, overlaps warp-0 serial work) ----
    int a0 = 0, rem0 = tid;
    while (rem0 >= 63 - a0) { rem0 -= 63 - a0; ++a0; }

    int piv_a = 0, piv_b = 0, mj0 = 0, mj1 = 0;

    if (wrp == 0) {
        // ---- permuted generator columns, 4 per lane, in registers ----
        int i0 = s_idx[lane], i1i = s_idx[32 + lane],
            i2i = s_idx[64 + lane], i3i = s_idx[96 + lane];
        #define LOADCOL(ix) ( (unsigned long long)(s_gmq[0][ix] | (s_gmq[1][ix] << 16)) \
                           | ((unsigned long long)(s_gmq[2][ix] | (s_gmq[3][ix] << 16)) << 32) )
        unsigned long long c0 = LOADCOL(i0);
        unsigned long long c1 = LOADCOL(i1i);
        unsigned long long c2 = LOADCOL(i2i);
        unsigned long long c3 = LOADCOL(i3i);
        #undef LOADCOL

        // ---- GF(2) Gauss-Jordan with batched ballot maintenance ----
        // Invariant: B0[m]/B1[m] = 128-col ballot of bit-row (base+m).
        // After step i with broadcast column colp:
        //   B_m ^= (colp bit m) ? B_i : 0   (scalar, off the shfl chain)
        unsigned long long pm0 = 0ull, pm1 = 0ull;
        for (int base = 0; base < K; base += 8) {
            unsigned long long B0[8], B1[8];
            #pragma unroll
            for (int m = 0; m < 8; ++m) {
                const unsigned long long bm = 1ull << (base + m);
                unsigned t0 = __ballot_sync(FULLM, (c0 & bm) != 0ull);
                unsigned t1 = __ballot_sync(FULLM, (c1 & bm) != 0ull);
                unsigned t2 = __ballot_sync(FULLM, (c2 & bm) != 0ull);
                unsigned t3 = __ballot_sync(FULLM, (c3 & bm) != 0ull);
                B0[m] = (unsigned long long)t0 | ((unsigned long long)t1 << 32);
                B1[m] = (unsigned long long)t2 | ((unsigned long long)t3 << 32);
            }
            #pragma unroll
            for (int s = 0; s < 8; ++s) {
                const int i = base + s;
                const unsigned long long bi = 1ull << i;
                int p = B0[s] ? (__ffsll((long long)B0[s]) - 1)
                              : (B1[s] ? 63 + __ffsll((long long)B1[s]) : 0);
                const int q = p >> 5;                         // uniform
                unsigned long long tA = (q & 2) ? c2 : c0;
                unsigned long long tB = (q & 2) ? c3 : c1;
                unsigned long long myc = (q & 1) ? tB : tA;
                unsigned long long colp = __shfl_sync(FULLM, myc, p & 31);
                unsigned long long mask = colp & ~bi;
                if (c0 & bi) c0 ^= mask;
                if (c1 & bi) c1 ^= mask;
                if (c2 & bi) c2 ^= mask;
                if (c3 & bi) c3 ^= mask;
                if (p < 64) pm0 |= 1ull << p; else pm1 |= 1ull << (p - 64);
                if (lane == (i & 31)) { if (i < 32) piv_a = p; else piv_b = p; }
                #pragma unroll
                for (int m = s + 1; m < 8; ++m) {
                    if ((colp >> (base + m)) & 1ull) { B0[m] ^= B0[s]; B1[m] ^= B1[s]; }
                }
            }
        }

        // ---- info flip-costs + hard decisions ----
        float li_a = s_key[piv_a];
        float li_b = s_key[piv_b];
        s_dinfo[lane]      = fabsf(li_a);
        s_dinfo[lane + 32] = fabsf(li_b);
        unsigned ub0 = __ballot_sync(FULLM, li_a > 0.0f);
        unsigned ub1 = __ballot_sync(FULLM, li_b > 0.0f);
        unsigned long long u64 =
            (unsigned long long)ub0 | ((unsigned long long)ub1 << 32);
        if (lane == 0) s_u = u64;

        // ---- parity positions (ascending non-pivot), 2 per lane, via FNS ----
        unsigned long long nm0 = ~pm0, nm1 = ~pm1;
        int cnt0 = __popcll(nm0);
        mj0 = (lane < cnt0) ? nth_set64(nm0, lane)
                            : 64 + nth_set64(nm1, lane - cnt0);
        {
            int j = lane + 32;
            mj1 = (j < cnt0) ? nth_set64(nm0, j)
                             : 64 + nth_set64(nm1, j - cnt0);
        }

        // ---- gather parity columns ----
        unsigned long long pc0, pc1;
        {
            unsigned long long v0 = __shfl_sync(FULLM, c0, mj0 & 31);
            unsigned long long v1 = __shfl_sync(FULLM, c1, mj0 & 31);
            unsigned long long v2 = __shfl_sync(FULLM, c2, mj0 & 31);
            unsigned long long v3 = __shfl_sync(FULLM, c3, mj0 & 31);
            int q = mj0 >> 5;
            unsigned long long tA = (q & 2) ? v2 : v0;
            unsigned long long tB = (q & 2) ? v3 : v1;
            pc0 = (q & 1) ? tB : tA;
            v0 = __shfl_sync(FULLM, c0, mj1 & 31);
            v1 = __shfl_sync(FULLM, c1, mj1 & 31);
            v2 = __shfl_sync(FULLM, c2, mj1 & 31);
            v3 = __shfl_sync(FULLM, c3, mj1 & 31);
            q = mj1 >> 5;
            tA = (q & 2) ? v2 : v0;
            tB = (q & 2) ? v3 : v1;
            pc1 = (q & 1) ? tB : tA;
        }

        // ---- base parity bits + parity flip-costs ----
        int cb0 = (int)(__popcll(pc0 & u64) & 1ull);
        int cb1 = (int)(__popcll(pc1 & u64) & 1ull);
        unsigned cpb0 = __ballot_sync(FULLM, cb0);
        unsigned cpb1 = __ballot_sync(FULLM, cb1);
        if (lane == 0)
            s_Cp = (unsigned long long)cpb0 | ((unsigned long long)cpb1 << 32);
        s_dpar[lane]      = s_key[mj0] * (2.0f * (float)cb0 - 1.0f);
        s_dpar[lane + 32] = s_key[mj1] * (2.0f * (float)cb1 - 1.0f);

        // ---- publish parity columns for parallel transpose ----
        s_k64[lane]      = pc0;
        s_k64[32 + lane] = pc1;
    }
    __syncthreads();

    // ==== overlapped: warps 0-3 transpose, warps 4-11 build tables ====
    if (wrp < 4) {
        unsigned long long q0 = s_k64[lane];
        unsigned long long q1 = s_k64[32 + lane];
        const int base = wrp << 4;
        #pragma unroll
        for (int r = 0; r < 16; ++r) {
            const int i = base + r;
            unsigned r0 = __ballot_sync(FULLM, (q0 >> i) & 1ull);
            unsigned r1 = __ballot_sync(FULLM, (q1 >> i) & 1ull);
            if (lane == r)
                s_P[i] = (unsigned long long)r0 | ((unsigned long long)r1 << 32);
        }
    } else if (wrp < 12) {
        // one vv per thread (threads 128..383 cover vv 0..255), 8 sub-tables each
        const unsigned vv = (unsigned)(tid - 128);
        int pos[8], nb = 0;
        unsigned tmp = vv;
        while (tmp) { pos[nb++] = __ffs(tmp) - 1; tmp &= tmp - 1; }
        #pragma unroll
        for (int bp = 0; bp < 8; ++bp) {
            const float* dp = s_dpar + bp * 8;
            float s = 0.0f;
            for (int qq = 0; qq < nb; ++qq) s += dp[pos[qq]];
            s_tab[bp * 256 + vv] = s;
        }
    }
    __syncthreads();

    // ---- candidate search across all 512 threads ----
    float best = 0.0f;      // base candidate id 0 seeded everywhere
    int bestId = 0;

    if (t >= 1 && tid < K) {
        int i1 = tid;
        unsigned long long m = s_P[i1];
        unsigned lo = (unsigned)m, hi = (unsigned)(m >> 32);
        float t0 = s_tab[         lo & 255 ] + s_tab[ 256 + ((lo >> 8) & 255)];
        float t1 = s_tab[ 512 + ((lo >> 16) & 255)] + s_tab[ 768 + (lo >> 24)];
        float t2 = s_tab[1024 + ( hi & 255)] + s_tab[1280 + ((hi >> 8) & 255)];
        float t3 = s_tab[1536 + ((hi >> 16) & 255)] + s_tab[1792 + (hi >> 24)];
        float sc = s_dinfo[i1] + ((t0 + t1) + (t2 + t3));
        if (sc < best) { best = sc; bestId = 1 + i1; }
    }
    if (t >= 2) {
        int a = a0, rem = rem0;
        for (int pp = tid; pp < NPAIRS; pp += NT) {
            int i1 = a, i2 = a + 1 + rem;
            unsigned long long m = s_P[i1] ^ s_P[i2];
            unsigned lo = (unsigned)m, hi = (unsigned)(m >> 32);
            float t0 = s_tab[         lo & 255 ] + s_tab[ 256 + ((lo >> 8) & 255)];
            float t1 = s_tab[ 512 + ((lo >> 16) & 255)] + s_tab[ 768 + (lo >> 24)];
            float t2 = s_tab[1024 + ( hi & 255)] + s_tab[1280 + ((hi >> 8) & 255)];
            float t3 = s_tab[1536 + ((hi >> 16) & 255)] + s_tab[1792 + (hi >> 24)];
            float sc = (s_dinfo[i1] + s_dinfo[i2]) + ((t0 + t1) + (t2 + t3));
            if (sc < best) { best = sc; bestId = 65 + pp; }
            rem += NT;
            while (a < 63 && rem >= 63 - a) { rem -= 63 - a; ++a; }
        }
    }

    // ---- warp reduce then 16-lane shfl reduce, lexicographic (score, id) ----
    for (int off = 16; off; off >>= 1) {
        float os = __shfl_down_sync(FULLM, best, off);
        int  oid = __shfl_down_sync(FULLM, bestId, off);
        if (os < best || (os == best && oid < bestId)) { best = os; bestId = oid; }
    }
    if (lane == 0) { s_bsc[wrp] = best; s_bid[wrp] = bestId; }
    __syncthreads();
    if (wrp == 0) {
        if (lane < 16) { best = s_bsc[lane]; bestId = s_bid[lane]; }
        else           { best = 3.4e38f; bestId = 0x7fffffff; }
        #pragma unroll
        for (int off = 8; off; off >>= 1) {
            float os = __shfl_down_sync(FULLM, best, off);
            int  oid = __shfl_down_sync(FULLM, bestId, off);
            if (os < best || (os == best && oid < bestId)) { best = os; bestId = oid; }
        }
        const int w = __shfl_sync(FULLM, bestId, 0);

        // ---- decode winner + scatter (warp 0) ----
        unsigned long long flip = 0ull, Px = 0ull;
        if (w >= 1 && w <= K) {
            flip = 1ull << (w - 1);
            Px = s_P[w - 1];
        } else if (w > K) {
            int pidx = w - (K + 1), a2 = 0;
            while (pidx >= 63 - a2) { pidx -= 63 - a2; ++a2; }
            int i1 = a2, i2 = a2 + 1 + pidx;
            flip = (1ull << i1) | (1ull << i2);
            Px = s_P[i1] ^ s_P[i2];
        }
        const unsigned long long cinfo = s_u ^ flip;
        const unsigned long long cpar  = s_Cp ^ Px;

        float* ob = out + b * N;
        ob[s_idx[piv_a]] = (float)((cinfo >> lane) & 1ull);
        ob[s_idx[piv_b]] = (float)((cinfo >> (lane + 32)) & 1ull);
        ob[s_idx[mj0]]   = (float)((cpar  >> lane) & 1ull);
        ob[s_idx[mj1]]   = (float)((cpar  >> (lane + 32)) & 1ull);
    }
}

extern "C" void kernel_launch(void* const* d_in, const int* in_sizes, int n_in,
                              void* d_out, int out_size) {
    const float* llrs = (const float*)d_in[0];
    const float* gm   = (const float*)d_in[1];
    const int*   t    = (n_in > 2) ? (const int*)d_in[2] : nullptr;
    int bs = in_sizes[0] / N;

    osd_kernel<<<bs, NT>>>(llrs, gm, t, (float*)d_out);
}

// round 14
// speedup vs baseline: 1.4939x; 1.4939x over previous
#include <cuda_runtime.h>
#include <cstdint>

#define N 128
#define K 64
#define NPAIRS 2016
#define LLRMAX 100.0f
#define FULLM 0xffffffffu
#define NT 512

__device__ __forceinline__ int nth_set64(unsigned long long w, int j) {
    unsigned lo = (unsigned)w, hi = (unsigned)(w >> 32);
    int c = __popc(lo);
    return (j < c) ? __fns(lo, 0, j + 1) : 32 + __fns(hi, 0, j - c + 1);
}

// order-preserving float -> u32 (ascending)
__device__ __forceinline__ unsigned f2ord(float f) {
    unsigned u = __float_as_uint(f);
    return (u & 0x80000000u) ? ~u : (u | 0x80000000u);
}

__global__ __launch_bounds__(NT) void osd_kernel(
    const float* __restrict__ llrs,
    const float* __restrict__ gm,
    const int* __restrict__ t_ptr,
    float* __restrict__ out)
{
    __shared__ float s_llr[N];
    __shared__ float s_key[N];                // llr_sort
    __shared__ int   s_idx[N];
    __shared__ unsigned s_gmq[4][N];          // 16 packed rows per quarter
    __shared__ unsigned long long s_k64[N];   // sort keys, then parity cols
    __shared__ unsigned short s_rp[4][N];     // rank partials
    __shared__ unsigned long long s_P[K];
    __shared__ float s_dinfo[K];
    __shared__ float s_dpar[K];
    __shared__ float s_tab[8 * 256];
    __shared__ unsigned long long s_u, s_Cp;
    __shared__ unsigned long long s_red[16];

    const int tid  = threadIdx.x;
    const int lane = tid & 31;
    const int wrp  = tid >> 5;
    const int b    = blockIdx.x;

    // ---- hoisted t load ----
    int t = 2;
    if (t_ptr) t = t_ptr[0];
    if (t < 0) t = 0;
    if (t > 2) t = 2;

    // ---- gm pack: each thread packs 16 rows of one column ----
    {
        const int quarter = tid >> 7;         // 0..3
        const int col  = tid & 127;
        const int rbase = quarter << 4;       // 0,16,32,48
        unsigned w = 0u;
        #pragma unroll
        for (int i = 0; i < 16; ++i)
            if (gm[(rbase + i) * N + col] > 0.5f) w |= (1u << i);
        s_gmq[quarter][col] = w;
    }

    // ---- keys for rank sort ----
    if (tid < N) {
        float v = llrs[b * N + tid];
        v = fminf(fmaxf(v, -LLRMAX), LLRMAX);
        s_llr[tid] = v;
        s_k64[tid] = ((unsigned long long)__float_as_uint(fabsf(v)) << 32) |
                     (unsigned long long)(127 - tid);
    }
    __syncthreads();

    // ---- rank sort: thread (i, q) counts chunk q's keys greater than key i ----
    {
        const int i = tid & 127, q = tid >> 7;
        const unsigned long long ki = s_k64[i];
        const unsigned long long* base = s_k64 + q * 32;
        int cnt = 0;
        #pragma unroll
        for (int j = 0; j < 32; ++j) cnt += (base[j] > ki);
        s_rp[q][i] = (unsigned short)cnt;
    }
    __syncthreads();
    if (tid < N) {
        int r = s_rp[0][tid] + s_rp[1][tid] + s_rp[2][tid] + s_rp[3][tid];
        s_idx[r] = tid;          // rank r (descending) holds original index tid
        s_key[r] = s_llr[tid];
    }
    __syncthreads();

    // ---- pair decomposition (pure ALU, overlaps warp-0 serial work) ----
    int a0 = 0, rem0 = tid;
    while (rem0 >= 63 - a0) { rem0 -= 63 - a0; ++a0; }

    int piv_a = 0, piv_b = 0, mj0 = 0, mj1 = 0;

    if (wrp == 0) {
        // ---- permuted generator columns, 4 per lane, in registers ----
        int i0 = s_idx[lane], i1i = s_idx[32 + lane],
            i2i = s_idx[64 + lane], i3i = s_idx[96 + lane];
        #define LOADCOL(ix) ( (unsigned long long)(s_gmq[0][ix] | (s_gmq[1][ix] << 16)) \
                           | ((unsigned long long)(s_gmq[2][ix] | (s_gmq[3][ix] << 16)) << 32) )
        unsigned long long c0 = LOADCOL(i0);
        unsigned long long c1 = LOADCOL(i1i);
        unsigned long long c2 = LOADCOL(i2i);
        unsigned long long c3 = LOADCOL(i3i);
        #undef LOADCOL

        // ---- GF(2) Gauss-Jordan, column-wise, single shfl per step ----
        unsigned long long pm0 = 0ull, pm1 = 0ull;
        for (int i = 0; i < K; ++i) {
            const unsigned long long bi = 1ull << i;
            unsigned b0 = __ballot_sync(FULLM, (c0 & bi) != 0ull);
            unsigned b1 = __ballot_sync(FULLM, (c1 & bi) != 0ull);
            unsigned long long bb = (unsigned long long)b0 |
                                    ((unsigned long long)b1 << 32);
            int p;
            if (bb) {
                p = __ffsll((long long)bb) - 1;
            } else {
                unsigned b2 = __ballot_sync(FULLM, (c2 & bi) != 0ull);
                unsigned b3 = __ballot_sync(FULLM, (c3 & bi) != 0ull);
                unsigned long long bb2 = (unsigned long long)b2 |
                                         ((unsigned long long)b3 << 32);
                p = bb2 ? (63 + __ffsll((long long)bb2)) : 0;
            }
            const int q = p >> 5;                         // uniform
            unsigned long long tA = (q & 2) ? c2 : c0;
            unsigned long long tB = (q & 2) ? c3 : c1;
            unsigned long long myc = (q & 1) ? tB : tA;
            unsigned long long colp = __shfl_sync(FULLM, myc, p & 31);
            unsigned long long mask = colp & ~bi;
            if (c0 & bi) c0 ^= mask;
            if (c1 & bi) c1 ^= mask;
            if (c2 & bi) c2 ^= mask;
            if (c3 & bi) c3 ^= mask;
            if (p < 64) pm0 |= 1ull << p; else pm1 |= 1ull << (p - 64);
            if (lane == (i & 31)) { if (i < 32) piv_a = p; else piv_b = p; }
        }

        // ---- info flip-costs + hard decisions ----
        float li_a = s_key[piv_a];
        float li_b = s_key[piv_b];
        s_dinfo[lane]      = fabsf(li_a);
        s_dinfo[lane + 32] = fabsf(li_b);
        unsigned ub0 = __ballot_sync(FULLM, li_a > 0.0f);
        unsigned ub1 = __ballot_sync(FULLM, li_b > 0.0f);
        unsigned long long u64 =
            (unsigned long long)ub0 | ((unsigned long long)ub1 << 32);
        if (lane == 0) s_u = u64;

        // ---- parity positions (ascending non-pivot), 2 per lane, via FNS ----
        unsigned long long nm0 = ~pm0, nm1 = ~pm1;
        int cnt0 = __popcll(nm0);
        mj0 = (lane < cnt0) ? nth_set64(nm0, lane)
                            : 64 + nth_set64(nm1, lane - cnt0);
        {
            int j = lane + 32;
            mj1 = (j < cnt0) ? nth_set64(nm0, j)
                             : 64 + nth_set64(nm1, j - cnt0);
        }

        // ---- gather parity columns ----
        unsigned long long pc0, pc1;
        {
            unsigned long long v0 = __shfl_sync(FULLM, c0, mj0 & 31);
            unsigned long long v1 = __shfl_sync(FULLM, c1, mj0 & 31);
            unsigned long long v2 = __shfl_sync(FULLM, c2, mj0 & 31);
            unsigned long long v3 = __shfl_sync(FULLM, c3, mj0 & 31);
            int q = mj0 >> 5;
            unsigned long long tA = (q & 2) ? v2 : v0;
            unsigned long long tB = (q & 2) ? v3 : v1;
            pc0 = (q & 1) ? tB : tA;
            v0 = __shfl_sync(FULLM, c0, mj1 & 31);
            v1 = __shfl_sync(FULLM, c1, mj1 & 31);
            v2 = __shfl_sync(FULLM, c2, mj1 & 31);
            v3 = __shfl_sync(FULLM, c3, mj1 & 31);
            q = mj1 >> 5;
            tA = (q & 2) ? v2 : v0;
            tB = (q & 2) ? v3 : v1;
            pc1 = (q & 1) ? tB : tA;
        }

        // ---- base parity bits + parity flip-costs ----
        int cb0 = (int)(__popcll(pc0 & u64) & 1ull);
        int cb1 = (int)(__popcll(pc1 & u64) & 1ull);
        unsigned cpb0 = __ballot_sync(FULLM, cb0);
        unsigned cpb1 = __ballot_sync(FULLM, cb1);
        if (lane == 0)
            s_Cp = (unsigned long long)cpb0 | ((unsigned long long)cpb1 << 32);
        s_dpar[lane]      = s_key[mj0] * (2.0f * (float)cb0 - 1.0f);
        s_dpar[lane + 32] = s_key[mj1] * (2.0f * (float)cb1 - 1.0f);

        // ---- publish parity columns for parallel transpose ----
        s_k64[lane]      = pc0;
        s_k64[32 + lane] = pc1;
    }
    __syncthreads();

    // ==== overlapped: warps 0-3 transpose, warps 4-11 build tables ====
    if (wrp < 4) {
        unsigned long long q0 = s_k64[lane];
        unsigned long long q1 = s_k64[32 + lane];
        const int base = wrp << 4;
        #pragma unroll
        for (int r = 0; r < 16; ++r) {
            const int i = base + r;
            unsigned r0 = __ballot_sync(FULLM, (q0 >> i) & 1ull);
            unsigned r1 = __ballot_sync(FULLM, (q1 >> i) & 1ull);
            if (lane == r)
                s_P[i] = (unsigned long long)r0 | ((unsigned long long)r1 << 32);
        }
    } else if (wrp < 12) {
        // one vv per thread (threads 128..383 cover vv 0..255), 8 sub-tables each
        const unsigned vv = (unsigned)(tid - 128);
        int pos[8], nb = 0;
        unsigned tmp = vv;
        while (tmp) { pos[nb++] = __ffs(tmp) - 1; tmp &= tmp - 1; }
        #pragma unroll
        for (int bp = 0; bp < 8; ++bp) {
            const float* dp = s_dpar + bp * 8;
            float s = 0.0f;
            for (int qq = 0; qq < nb; ++qq) s += dp[pos[qq]];
            s_tab[bp * 256 + vv] = s;
        }
    }
    __syncthreads();

    // ---- candidate search across all 512 threads ----
    // packed (order(score) << 32) | cid; min == lexicographic (score, cid) min
    unsigned long long bestPk =
        ((unsigned long long)f2ord(0.0f) << 32);   // base candidate id 0

    if (t >= 1 && tid < K) {
        int i1 = tid;
        unsigned long long m = s_P[i1];
        unsigned lo = (unsigned)m, hi = (unsigned)(m >> 32);
        float t0 = s_tab[         lo & 255 ] + s_tab[ 256 + ((lo >> 8) & 255)];
        float t1 = s_tab[ 512 + ((lo >> 16) & 255)] + s_tab[ 768 + (lo >> 24)];
        float t2 = s_tab[1024 + ( hi & 255)] + s_tab[1280 + ((hi >> 8) & 255)];
        float t3 = s_tab[1536 + ((hi >> 16) & 255)] + s_tab[1792 + (hi >> 24)];
        float sc = s_dinfo[i1] + ((t0 + t1) + (t2 + t3));
        unsigned long long pk = ((unsigned long long)f2ord(sc) << 32) |
                                (unsigned)(1 + i1);
        if (pk < bestPk) bestPk = pk;
    }
    if (t >= 2) {
        int a = a0, rem = rem0;
        for (int pp = tid; pp < NPAIRS; pp += NT) {
            int i1 = a, i2 = a + 1 + rem;
            unsigned long long m = s_P[i1] ^ s_P[i2];
            unsigned lo = (unsigned)m, hi = (unsigned)(m >> 32);
            float t0 = s_tab[         lo & 255 ] + s_tab[ 256 + ((lo >> 8) & 255)];
            float t1 = s_tab[ 512 + ((lo >> 16) & 255)] + s_tab[ 768 + (lo >> 24)];
            float t2 = s_tab[1024 + ( hi & 255)] + s_tab[1280 + ((hi >> 8) & 255)];
            float t3 = s_tab[1536 + ((hi >> 16) & 255)] + s_tab[1792 + (hi >> 24)];
            float sc = (s_dinfo[i1] + s_dinfo[i2]) + ((t0 + t1) + (t2 + t3));
            unsigned long long pk = ((unsigned long long)f2ord(sc) << 32) |
                                    (unsigned)(65 + pp);
            if (pk < bestPk) bestPk = pk;
            rem += NT;
            while (a < 63 && rem >= 63 - a) { rem -= 63 - a; ++a; }
        }
    }

    // ---- warp reduce then 16-lane shfl reduce over packed u64 ----
    #pragma unroll
    for (int off = 16; off; off >>= 1) {
        unsigned long long o = __shfl_down_sync(FULLM, bestPk, off);
        if (o < bestPk) bestPk = o;
    }
    if (lane == 0) s_red[wrp] = bestPk;
    __syncthreads();
    if (wrp == 0) {
        bestPk = (lane < 16) ? s_red[lane] : 0xffffffffffffffffull;
        #pragma unroll
        for (int off = 8; off; off >>= 1) {
            unsigned long long o = __shfl_down_sync(FULLM, bestPk, off);
            if (o < bestPk) bestPk = o;
        }
        const int w = (int)(unsigned)__shfl_sync(FULLM, bestPk, 0);

        // ---- decode winner + scatter (warp 0) ----
        unsigned long long flip = 0ull, Px = 0ull;
        if (w >= 1 && w <= K) {
            flip = 1ull << (w - 1);
            Px = s_P[w - 1];
        } else if (w > K) {
            int pidx = w - (K + 1), a2 = 0;
            while (pidx >= 63 - a2) { pidx -= 63 - a2; ++a2; }
            int i1 = a2, i2 = a2 + 1 + pidx;
            flip = (1ull << i1) | (1ull << i2);
            Px = s_P[i1] ^ s_P[i2];
        }
        const unsigned long long cinfo = s_u ^ flip;
        const unsigned long long cpar  = s_Cp ^ Px;

        float* ob = out + b * N;
        ob[s_idx[piv_a]] = (float)((cinfo >> lane) & 1ull);
        ob[s_idx[piv_b]] = (float)((cinfo >> (lane + 32)) & 1ull);
        ob[s_idx[mj0]]   = (float)((cpar  >> lane) & 1ull);
        ob[s_idx[mj1]]   = (float)((cpar  >> (lane + 32)) & 1ull);
    }
}

extern "C" void kernel_launch(void* const* d_in, const int* in_sizes, int n_in,
                              void* d_out, int out_size) {
    const float* llrs = (const float*)d_in[0];
    const float* gm   = (const float*)d_in[1];
    const int*   t    = (n_in > 2) ? (const int*)d_in[2] : nullptr;
    int bs = in_sizes[0] / N;

    osd_kernel<<<bs, NT>>>(llrs, gm, t, (float*)d_out);
}